// round 16
// baseline (speedup 1.0000x reference)
#include <cuda_runtime.h>
#include <cuda_fp16.h>
#include <cstdint>

// Problem constants
#define NTOK 65536
#define IN   512
#define OUT  512
#define NE   8
#define NS   64

// GEMM tiling (r11 config: 4 CTAs/SM, 4 warps of 64x32)
#define TM 128
#define TN 64
#define KC 64
#define NCHUNK (IN / KC)          // 8
#define MAXT 576
#define LDSS 144                  // 128B data + 16B pad: conflict-free ldmatrix

#define A_PLANE (TM * LDSS)       // 18432
#define B_PLANE (TN * LDSS)       // 9216
#define OFF_B   A_PLANE
#define STAGE_BYTES (A_PLANE + B_PLANE)       // 27648
#define OFF_PERM (2 * STAGE_BYTES)            // 55296
#define GSMEM (OFF_PERM + 512)                // 55808  (4 CTAs/SM)

// ---------------- device scratch (static; no allocation) ---------------------
__device__ __half g_Mh[(size_t)NS * OUT * IN];
__device__ int g_counts[NS];          // zeroed by plan block after use
__device__ int g_cursor[NS];
__device__ int g_perm[NTOK];
__device__ int g_tile_sys[MAXT];
__device__ int g_tile_start[MAXT];
__device__ int g_tile_rows[MAXT];
__device__ int g_hist_done;           // reset by plan block
__device__ int g_plan_flag;           // reset by gemm block (0,0)

// ---------------- helpers -----------------------------------------------------
__device__ __forceinline__ uint32_t smem_u32(const void* p) {
    uint32_t a;
    asm("{ .reg .u64 t; cvta.to.shared.u64 t, %1; cvt.u32.u64 %0, t; }"
        : "=r"(a) : "l"(p));
    return a;
}
__device__ __forceinline__ void cpa16(uint32_t dst, const void* src) {
    asm volatile("cp.async.cg.shared.global [%0], [%1], 16;"
                 :: "r"(dst), "l"(src) : "memory");
}
__device__ __forceinline__ void sts128(uint32_t addr, uint32_t a, uint32_t b,
                                       uint32_t c, uint32_t d) {
    asm volatile("st.shared.v4.b32 [%0], {%1,%2,%3,%4};"
                 :: "r"(addr), "r"(a), "r"(b), "r"(c), "r"(d) : "memory");
}
__device__ __forceinline__ void ldsm4(uint32_t* r, uint32_t addr) {
    asm volatile("ldmatrix.sync.aligned.m8n8.x4.shared.b16 {%0,%1,%2,%3}, [%4];"
                 : "=r"(r[0]), "=r"(r[1]), "=r"(r[2]), "=r"(r[3]) : "r"(addr));
}
__device__ __forceinline__ void mma16816(float* c, const uint32_t* a,
                                         uint32_t b0, uint32_t b1) {
    asm volatile(
        "mma.sync.aligned.m16n8k16.row.col.f32.f16.f16.f32 "
        "{%0,%1,%2,%3}, {%4,%5,%6,%7}, {%8,%9}, {%0,%1,%2,%3};"
        : "+f"(c[0]), "+f"(c[1]), "+f"(c[2]), "+f"(c[3])
        : "r"(a[0]), "r"(a[1]), "r"(a[2]), "r"(a[3]), "r"(b0), "r"(b1));
}
__device__ __forceinline__ uint2 round4h(float4 v) {
    __half2 h01 = __floats2half2_rn(v.x, v.y);
    __half2 h23 = __floats2half2_rn(v.z, v.w);
    return make_uint2(*(uint32_t*)&h01, *(uint32_t*)&h23);
}

// ---------------- kernel 1: fused prep (NO x conversion) ----------------------
// blocks 0..63:    hist (last-done block runs plan inline, sets g_plan_flag)
// blocks 64..127:  scatter (spins on flag for bases)
// blocks 128..255: mix weights -> fp16
__global__ __launch_bounds__(256) void prep_kernel(const int* __restrict__ bi,
                                                   const float* __restrict__ W,
                                                   const float* __restrict__ coeff) {
    int bx = blockIdx.x;
    int tid = threadIdx.x;

    if (bx < 64) {
        // ---- histogram over tokens [bx*1024, +1024) ----
        __shared__ int h[NS];
        __shared__ int lastdone;
        if (tid < NS) h[tid] = 0;
        __syncthreads();
        int base = bx * 1024;
#pragma unroll
        for (int j = 0; j < 4; ++j)
            atomicAdd(&h[bi[base + j * 256 + tid]], 1);
        __syncthreads();
        if (tid < NS && h[tid] != 0) atomicAdd(&g_counts[tid], h[tid]);
        __threadfence();
        __syncthreads();
        if (tid == 0) lastdone = atomicAdd(&g_hist_done, 1);
        __syncthreads();
        if (lastdone != 63) return;

        // ---- plan (runs in the last-finishing hist block) ----
        __threadfence();
        __shared__ int cnt[NS], offs[NS], tbase[NS];
        if (tid < NS) cnt[tid] = g_counts[tid];
        __syncthreads();
        if (tid == 0) {
            int off = 0, tb = 0;
            for (int s = 0; s < NS; ++s) {
                offs[s] = off; tbase[s] = tb;
                off += cnt[s];
                tb  += (cnt[s] + TM - 1) / TM;
            }
        }
        __syncthreads();
        for (int i = tid; i < MAXT; i += 256) g_tile_rows[i] = 0;
        __syncthreads();
        if (tid < NS) {
            int s = tid, c = cnt[s], nt = (c + TM - 1) / TM;
            int tb = tbase[s], off = offs[s];
            g_cursor[s] = off;
            for (int k = 0; k < nt; ++k) {
                g_tile_sys[tb + k]   = s;
                g_tile_start[tb + k] = off + k * TM;
                int rem = c - k * TM;
                g_tile_rows[tb + k]  = rem < TM ? rem : TM;
            }
            g_counts[s] = 0;           // reset for next graph replay
        }
        if (tid == 0) g_hist_done = 0; // reset for next graph replay
        __threadfence();
        __syncthreads();
        if (tid == 0) atomicExch(&g_plan_flag, 1);   // release
    } else if (bx < 128) {
        // ---- scatter tokens [(bx-64)*1024, +1024): write g_perm ----
        __shared__ int lc[NS], lbase[NS];
        if (tid < NS) lc[tid] = 0;
        __syncthreads();
        int base = (bx - 64) * 1024;
        int myn[4], mys[4], myr[4];
#pragma unroll
        for (int j = 0; j < 4; ++j) {
            int n = base + j * 256 + tid;
            int s = bi[n];
            myn[j] = n; mys[j] = s;
            myr[j] = atomicAdd(&lc[s], 1);
        }
        __syncthreads();
        if (tid == 0) {
            while (atomicAdd(&g_plan_flag, 0) == 0) __nanosleep(200);
        }
        __syncthreads();
        __threadfence();               // acquire
        if (tid < NS && lc[tid] > 0) lbase[tid] = atomicAdd(&g_cursor[tid], lc[tid]);
        __syncthreads();
#pragma unroll
        for (int j = 0; j < 4; ++j)
            g_perm[lbase[mys[j]] + myr[j]] = myn[j];
    } else {
        // ---- mix: M[s] = sum_e c[s,e] * W[e], rounded fp16 ----
        __shared__ float sc[NS * NE];
        for (int i = tid; i < NS * NE; i += 256) sc[i] = coeff[i];
        __syncthreads();
#pragma unroll
        for (int half = 0; half < 2; ++half) {
            int idx = (bx - 128) * 512 + half * 256 + tid;  // over OUT*IN/4
            int o  = idx >> 7;
            int q  = idx & 127;
            int i4 = q * 4;
            float4 w[NE];
#pragma unroll
            for (int e = 0; e < NE; ++e)
                w[e] = *(const float4*)(W + (size_t)e * OUT * IN + o * IN + i4);
#pragma unroll 4
            for (int s = 0; s < NS; ++s) {
                float4 acc = make_float4(0.f, 0.f, 0.f, 0.f);
#pragma unroll
                for (int e = 0; e < NE; ++e) {
                    float c = sc[s * NE + e];
                    acc.x = fmaf(c, w[e].x, acc.x);
                    acc.y = fmaf(c, w[e].y, acc.y);
                    acc.z = fmaf(c, w[e].z, acc.z);
                    acc.w = fmaf(c, w[e].w, acc.w);
                }
                ((uint2*)(g_Mh + (size_t)(s * OUT + o) * IN))[q] = round4h(acc);
            }
        }
    }
}

// ---------------- kernel 2: grouped GEMM, A converted in-kernel ---------------
// r11 mainloop shape (CTA 128x64, warp 64x32, 2-stage, kk-dbuf) with A loaded
// as fp32 from x (LDG.128 x2 -> cvt -> STS.128), phased 2 rows at a time so
// only 16 fp32 regs are in flight. B unchanged (cp.async of fp16 g_Mh).
__global__ __launch_bounds__(128, 4) void gemm_kernel(const float* __restrict__ x,
                                                      const float* __restrict__ bias,
                                                      float* __restrict__ out) {
    if (blockIdx.x == 0 && blockIdx.y == 0 && threadIdx.x == 0)
        g_plan_flag = 0;               // reset for next graph replay

    int bt = blockIdx.y;
    int rows = g_tile_rows[bt];
    if (rows == 0) return;
    int sys       = g_tile_sys[bt];
    int row_start = g_tile_start[bt];
    int col0      = blockIdx.x * TN;

    extern __shared__ __align__(16) char smem[];
    uint32_t sm = smem_u32(smem);
    int tid = threadIdx.x, lane = tid & 31, wid = tid >> 5;
    int wm = wid >> 1, wn = wid & 1;      // 2 x 2 warp grid

    int* sperm = (int*)(smem + OFF_PERM);
    if (tid < TM) {
        int rsi = row_start + tid;
        if (rsi > NTOK - 1) rsi = NTOK - 1;
        sperm[tid] = g_perm[rsi];
    }

    // ---- hoisted loader pointers (fp32 x rows, perm-gathered) ----
    int row16 = tid >> 3;     // 0..15
    int seg   = tid & 7;      // 8-float segment within the k-chunk
    const float* apt[8];
#pragma unroll
    for (int h = 0; h < 8; ++h) {
        int rsi = row_start + row16 + h * 16;
        if (rsi > NTOK - 1) rsi = NTOK - 1;
        int tok = __ldg(&g_perm[rsi]);
        apt[h] = x + (size_t)tok * IN + seg * 8;
    }
    const __half* bpt = g_Mh + (size_t)sys * OUT * IN
                      + (size_t)(col0 + row16) * IN + seg * 8;
    uint32_t dstA = sm + row16 * LDSS + seg * 16;

    // convert one A row-pair (phase): 2 rows x 8 fp32 -> 8 halves each
    auto conv_row = [&](uint32_t st, int h, float4 f0, float4 f1) {
        __half2 p0 = __floats2half2_rn(f0.x, f0.y);
        __half2 p1 = __floats2half2_rn(f0.z, f0.w);
        __half2 p2 = __floats2half2_rn(f1.x, f1.y);
        __half2 p3 = __floats2half2_rn(f1.z, f1.w);
        sts128(st + dstA + h * 16 * LDSS,
               *(uint32_t*)&p0, *(uint32_t*)&p1, *(uint32_t*)&p2, *(uint32_t*)&p3);
    };

    auto load_B = [&](uint32_t stoff, int c) {
#pragma unroll
        for (int h = 0; h < 4; ++h)
            cpa16(stoff + dstA + OFF_B + h * 16 * LDSS, bpt + (size_t)h * 16 * IN + c * KC);
        asm volatile("cp.async.commit_group;" ::: "memory");
    };

    float acc[4][4][4];
#pragma unroll
    for (int mf = 0; mf < 4; ++mf)
#pragma unroll
        for (int nf = 0; nf < 4; ++nf)
#pragma unroll
            for (int r = 0; r < 4; ++r) acc[mf][nf][r] = 0.f;

    // ---- prologue: B(0) async; A(0) direct load+convert into stage 0 ----
    load_B(0, 0);
#pragma unroll
    for (int h = 0; h < 8; ++h) {
        const float4* a4 = (const float4*)(apt[h]);
        conv_row(0, h, a4[0], a4[1]);
    }

    int lrow = lane & 15, kseg = lane >> 4;
    uint32_t a_base = sm + (uint32_t)((wm * 64 + lrow) * LDSS + kseg * 16);
    uint32_t b_base = sm + (uint32_t)(OFF_B + (wn * 32 + lrow) * LDSS + kseg * 16);

    uint32_t aa[2][4][4], bb[2][2][4];
    float4 pa0, pa1, pa2, pa3;           // phase staging: 2 rows x 2 float4

#pragma unroll
    for (int c = 0; c < NCHUNK; ++c) {
        asm volatile("cp.async.wait_group 0;" ::: "memory");
        __syncthreads();
        bool pf = (c + 1 < NCHUNK);
        uint32_t so1 = (uint32_t)(((c + 1) & 1) * STAGE_BYTES);
        if (pf) {
            load_B(so1, c + 1);
            // issue phase 0 LDGs (rows 0,1 of chunk c+1)
            const float4* r0 = (const float4*)(apt[0] + (c + 1) * KC);
            const float4* r1 = (const float4*)(apt[1] + (c + 1) * KC);
            pa0 = r0[0]; pa1 = r0[1]; pa2 = r1[0]; pa3 = r1[1];
        }

        uint32_t so = (uint32_t)((c & 1) * STAGE_BYTES);

#pragma unroll
        for (int mf = 0; mf < 4; ++mf)
            ldsm4(aa[0][mf], a_base + so + mf * 16 * LDSS);
#pragma unroll
        for (int bf = 0; bf < 2; ++bf)
            ldsm4(bb[0][bf], b_base + so + bf * 16 * LDSS);

#pragma unroll
        for (int kk = 0; kk < 4; ++kk) {
            int cur = kk & 1;
            if (kk < 3) {
                int nxt = cur ^ 1;
#pragma unroll
                for (int mf = 0; mf < 4; ++mf)
                    ldsm4(aa[nxt][mf], a_base + so + mf * 16 * LDSS + (kk + 1) * 32);
#pragma unroll
                for (int bf = 0; bf < 2; ++bf)
                    ldsm4(bb[nxt][bf], b_base + so + bf * 16 * LDSS + (kk + 1) * 32);
            }
#pragma unroll
            for (int mf = 0; mf < 4; ++mf)
#pragma unroll
                for (int nf = 0; nf < 4; ++nf)
                    mma16816(acc[mf][nf], aa[cur][mf],
                             bb[cur][nf >> 1][nf & 1], bb[cur][nf >> 1][(nf & 1) + 2]);
            // A prefetch pipeline for chunk c+1: convert phase kk, issue kk+1
            if (pf) {
                conv_row(so1, 2 * kk + 0, pa0, pa1);
                conv_row(so1, 2 * kk + 1, pa2, pa3);
                if (kk < 3) {
                    const float4* r0 = (const float4*)(apt[2 * kk + 2] + (c + 1) * KC);
                    const float4* r1 = (const float4*)(apt[2 * kk + 3] + (c + 1) * KC);
                    pa0 = r0[0]; pa1 = r0[1]; pa2 = r1[0]; pa3 = r1[1];
                }
            }
        }
    }

    // ---------------- epilogue: bias + scatter -------------------------------
    int g  = lane >> 2;
    int tc = (lane & 3) * 2;
    const float* bptr = bias + col0 + wn * 32 + tc;
    float2 bv[4];
#pragma unroll
    for (int nf = 0; nf < 4; ++nf)
        bv[nf] = make_float2(bptr[nf * 8], bptr[nf * 8 + 1]);

#pragma unroll
    for (int mf = 0; mf < 4; ++mf) {
#pragma unroll
        for (int rh = 0; rh < 2; ++rh) {
            int lr = wm * 64 + mf * 16 + rh * 8 + g;
            if (lr < rows) {
                float* orow = out + (size_t)sperm[lr] * OUT + col0 + wn * 32 + tc;
#pragma unroll
                for (int nf = 0; nf < 4; ++nf) {
                    float2 v = make_float2(acc[mf][nf][rh * 2]     + bv[nf].x,
                                           acc[mf][nf][rh * 2 + 1] + bv[nf].y);
                    *(float2*)(orow + nf * 8) = v;
                }
            }
        }
    }
}

// ---------------- launch -----------------------------------------------------
extern "C" void kernel_launch(void* const* d_in, const int* in_sizes, int n_in,
                              void* d_out, int out_size) {
    const float* x     = (const float*)d_in[0];
    const float* coeff = (const float*)d_in[1];
    const int*   bidx  = (const int*)d_in[2];
    const float* W     = (const float*)d_in[3];
    const float* bias  = (const float*)d_in[4];
    float*       out   = (float*)d_out;

    cudaFuncSetAttribute(gemm_kernel, cudaFuncAttributeMaxDynamicSharedMemorySize,
                         GSMEM);

    prep_kernel<<<256, 256>>>(bidx, W, coeff);
    gemm_kernel<<<dim3(OUT / TN, MAXT), 128, GSMEM>>>(x, bias, out);
}

// round 17
// speedup vs baseline: 1.4450x; 1.4450x over previous
#include <cuda_runtime.h>
#include <cuda_fp16.h>
#include <cstdint>

// Problem constants
#define NTOK 65536
#define IN   512
#define OUT  512
#define NE   8
#define NS   64

// GEMM tiling (4 CTAs/SM, 4 warps of 64x32) — verified optimum (r11/r14)
#define TM 128
#define TN 64
#define KC 64
#define NCHUNK (IN / KC)          // 8
#define MAXT 576
#define LDSS 144                  // 128B data + 16B pad: conflict-free ldmatrix

#define A_PLANE (TM * LDSS)       // 18432
#define B_PLANE (TN * LDSS)       // 9216
#define OFF_B   A_PLANE
#define STAGE_BYTES (A_PLANE + B_PLANE)       // 27648
#define OFF_PERM (2 * STAGE_BYTES)            // 55296
#define GSMEM (OFF_PERM + 512)                // 55808  (4 CTAs/SM)

// ---------------- device scratch (static; no allocation) ---------------------
__device__ __half g_xh[(size_t)NTOK * IN];    // fp16(x), ORIGINAL token order
__device__ __half g_Mh[(size_t)NS * OUT * IN];
__device__ int g_counts[NS];          // zeroed by plan block after use
__device__ int g_cursor[NS];
__device__ int g_perm[NTOK];
__device__ int g_tile_sys[MAXT];
__device__ int g_tile_start[MAXT];
__device__ int g_tile_rows[MAXT];
__device__ int g_hist_done;           // reset by plan block
__device__ int g_plan_flag;           // reset by gemm block (0,0)

// ---------------- helpers -----------------------------------------------------
__device__ __forceinline__ uint32_t smem_u32(const void* p) {
    uint32_t a;
    asm("{ .reg .u64 t; cvta.to.shared.u64 t, %1; cvt.u32.u64 %0, t; }"
        : "=r"(a) : "l"(p));
    return a;
}
__device__ __forceinline__ void cpa16(uint32_t dst, const void* src) {
    asm volatile("cp.async.cg.shared.global [%0], [%1], 16;"
                 :: "r"(dst), "l"(src) : "memory");
}
__device__ __forceinline__ void ldsm4(uint32_t* r, uint32_t addr) {
    asm volatile("ldmatrix.sync.aligned.m8n8.x4.shared.b16 {%0,%1,%2,%3}, [%4];"
                 : "=r"(r[0]), "=r"(r[1]), "=r"(r[2]), "=r"(r[3]) : "r"(addr));
}
__device__ __forceinline__ void mma16816(float* c, const uint32_t* a,
                                         uint32_t b0, uint32_t b1) {
    asm volatile(
        "mma.sync.aligned.m16n8k16.row.col.f32.f16.f16.f32 "
        "{%0,%1,%2,%3}, {%4,%5,%6,%7}, {%8,%9}, {%0,%1,%2,%3};"
        : "+f"(c[0]), "+f"(c[1]), "+f"(c[2]), "+f"(c[3])
        : "r"(a[0]), "r"(a[1]), "r"(a[2]), "r"(a[3]), "r"(b0), "r"(b1));
}
__device__ __forceinline__ uint2 round4h(float4 v) {
    __half2 h01 = __floats2half2_rn(v.x, v.y);
    __half2 h23 = __floats2half2_rn(v.z, v.w);
    return make_uint2(*(uint32_t*)&h01, *(uint32_t*)&h23);
}

// ---------------- kernel 1: fused prep ---------------------------------------
// blocks 0..63:    hist (last-done block runs plan inline, sets g_plan_flag)
// blocks 64..127:  scatter (spins on flag for bases)
// blocks 128..383: convert x -> fp16 (contiguous 256KB chunks)
// blocks 384..511: mix weights -> fp16
__global__ __launch_bounds__(256) void prep_kernel(const int* __restrict__ bi,
                                                   const float* __restrict__ x,
                                                   const float* __restrict__ W,
                                                   const float* __restrict__ coeff) {
    int bx = blockIdx.x;
    int tid = threadIdx.x;

    if (bx < 64) {
        // ---- histogram over tokens [bx*1024, +1024) ----
        __shared__ int h[NS];
        __shared__ int lastdone;
        if (tid < NS) h[tid] = 0;
        __syncthreads();
        int base = bx * 1024;
#pragma unroll
        for (int j = 0; j < 4; ++j)
            atomicAdd(&h[bi[base + j * 256 + tid]], 1);
        __syncthreads();
        if (tid < NS && h[tid] != 0) atomicAdd(&g_counts[tid], h[tid]);
        __threadfence();
        __syncthreads();
        if (tid == 0) lastdone = atomicAdd(&g_hist_done, 1);
        __syncthreads();
        if (lastdone != 63) return;

        // ---- plan (runs in the last-finishing hist block) ----
        __threadfence();
        __shared__ int cnt[NS], offs[NS], tbase[NS];
        if (tid < NS) cnt[tid] = g_counts[tid];
        __syncthreads();
        if (tid == 0) {
            int off = 0, tb = 0;
            for (int s = 0; s < NS; ++s) {
                offs[s] = off; tbase[s] = tb;
                off += cnt[s];
                tb  += (cnt[s] + TM - 1) / TM;
            }
        }
        __syncthreads();
        for (int i = tid; i < MAXT; i += 256) g_tile_rows[i] = 0;
        __syncthreads();
        if (tid < NS) {
            int s = tid, c = cnt[s], nt = (c + TM - 1) / TM;
            int tb = tbase[s], off = offs[s];
            g_cursor[s] = off;
            for (int k = 0; k < nt; ++k) {
                g_tile_sys[tb + k]   = s;
                g_tile_start[tb + k] = off + k * TM;
                int rem = c - k * TM;
                g_tile_rows[tb + k]  = rem < TM ? rem : TM;
            }
            g_counts[s] = 0;           // reset for next graph replay
        }
        if (tid == 0) g_hist_done = 0; // reset for next graph replay
        __threadfence();
        __syncthreads();
        if (tid == 0) atomicExch(&g_plan_flag, 1);   // release
    } else if (bx < 128) {
        // ---- scatter tokens [(bx-64)*1024, +1024): write g_perm ----
        __shared__ int lc[NS], lbase[NS];
        if (tid < NS) lc[tid] = 0;
        __syncthreads();
        int base = (bx - 64) * 1024;
        int myn[4], mys[4], myr[4];
#pragma unroll
        for (int j = 0; j < 4; ++j) {
            int n = base + j * 256 + tid;
            int s = bi[n];
            myn[j] = n; mys[j] = s;
            myr[j] = atomicAdd(&lc[s], 1);
        }
        __syncthreads();
        if (tid == 0) {
            while (atomicAdd(&g_plan_flag, 0) == 0) __nanosleep(200);
        }
        __syncthreads();
        __threadfence();               // acquire
        if (tid < NS && lc[tid] > 0) lbase[tid] = atomicAdd(&g_cursor[tid], lc[tid]);
        __syncthreads();
#pragma unroll
        for (int j = 0; j < 4; ++j)
            g_perm[lbase[mys[j]] + myr[j]] = myn[j];
    } else if (bx < 384) {
        // ---- convert x -> fp16, original order; contiguous streaming ----
        const float4* xin = (const float4*)x;
        uint2* xo = (uint2*)g_xh;
        int b0 = (bx - 128) * 32768 + tid;   // 32768 float4 per block
#pragma unroll 8
        for (int i = 0; i < 128; ++i) {
            int gidx = b0 + i * 256;
            xo[gidx] = round4h(xin[gidx]);
        }
    } else {
        // ---- mix: M[s] = sum_e c[s,e] * W[e], rounded fp16 ----
        __shared__ float sc[NS * NE];
        for (int i = tid; i < NS * NE; i += 256) sc[i] = coeff[i];
        __syncthreads();
#pragma unroll
        for (int half = 0; half < 2; ++half) {
            int idx = (bx - 384) * 512 + half * 256 + tid;  // over OUT*IN/4
            int o  = idx >> 7;
            int q  = idx & 127;
            int i4 = q * 4;
            float4 w[NE];
#pragma unroll
            for (int e = 0; e < NE; ++e)
                w[e] = *(const float4*)(W + (size_t)e * OUT * IN + o * IN + i4);
#pragma unroll 4
            for (int s = 0; s < NS; ++s) {
                float4 acc = make_float4(0.f, 0.f, 0.f, 0.f);
#pragma unroll
                for (int e = 0; e < NE; ++e) {
                    float c = sc[s * NE + e];
                    acc.x = fmaf(c, w[e].x, acc.x);
                    acc.y = fmaf(c, w[e].y, acc.y);
                    acc.z = fmaf(c, w[e].z, acc.z);
                    acc.w = fmaf(c, w[e].w, acc.w);
                }
                ((uint2*)(g_Mh + (size_t)(s * OUT + o) * IN))[q] = round4h(acc);
            }
        }
    }
}

// ---------------- kernel 2: grouped GEMM, fp16, 4 warps, 4 CTAs/SM ------------
// Verified optimum (129.1us): CTA 128x64; warp tile 64x32; 2-stage cp.async;
// kk double-buffer; A rows gathered via g_perm; chunk advance = immediates.
__global__ __launch_bounds__(128, 4) void gemm_kernel(const float* __restrict__ bias,
                                                      float* __restrict__ out) {
    if (blockIdx.x == 0 && blockIdx.y == 0 && threadIdx.x == 0)
        g_plan_flag = 0;               // reset for next graph replay

    int bt = blockIdx.y;
    int rows = g_tile_rows[bt];
    if (rows == 0) return;
    int sys       = g_tile_sys[bt];
    int row_start = g_tile_start[bt];
    int col0      = blockIdx.x * TN;

    extern __shared__ __align__(16) char smem[];
    uint32_t sm = smem_u32(smem);
    int tid = threadIdx.x, lane = tid & 31, wid = tid >> 5;
    int wm = wid >> 1, wn = wid & 1;      // 2 x 2 warp grid

    int* sperm = (int*)(smem + OFF_PERM);
    if (tid < TM) {
        int rsi = row_start + tid;
        if (rsi > NTOK - 1) rsi = NTOK - 1;
        sperm[tid] = g_perm[rsi];
    }

    // ---- hoisted loader pointers (computed ONCE; perm-gathered A rows) ----
    int row16 = tid >> 3;     // 0..15
    int seg   = tid & 7;
    const __half* apt[8];
#pragma unroll
    for (int h = 0; h < 8; ++h) {
        int rsi = row_start + row16 + h * 16;
        if (rsi > NTOK - 1) rsi = NTOK - 1;
        int tok = __ldg(&g_perm[rsi]);
        apt[h] = g_xh + (size_t)tok * IN + seg * 8;
    }
    const __half* bpt = g_Mh + (size_t)sys * OUT * IN
                      + (size_t)(col0 + row16) * IN + seg * 8;
    uint32_t dstA = sm + row16 * LDSS + seg * 16;

    auto load_chunk = [&](uint32_t stoff, int c) {
#pragma unroll
        for (int h = 0; h < 8; ++h)
            cpa16(stoff + dstA + h * 16 * LDSS, apt[h] + c * KC);
#pragma unroll
        for (int h = 0; h < 4; ++h)
            cpa16(stoff + dstA + OFF_B + h * 16 * LDSS, bpt + (size_t)h * 16 * IN + c * KC);
        asm volatile("cp.async.commit_group;" ::: "memory");
    };

    float acc[4][4][4];
#pragma unroll
    for (int mf = 0; mf < 4; ++mf)
#pragma unroll
        for (int nf = 0; nf < 4; ++nf)
#pragma unroll
            for (int r = 0; r < 4; ++r) acc[mf][nf][r] = 0.f;

    load_chunk(0, 0);

    int lrow = lane & 15, kseg = lane >> 4;
    uint32_t a_base = sm + (uint32_t)((wm * 64 + lrow) * LDSS + kseg * 16);
    uint32_t b_base = sm + (uint32_t)(OFF_B + (wn * 32 + lrow) * LDSS + kseg * 16);

    uint32_t aa[2][4][4], bb[2][2][4];

#pragma unroll
    for (int c = 0; c < NCHUNK; ++c) {
        asm volatile("cp.async.wait_group 0;" ::: "memory");
        __syncthreads();
        if (c + 1 < NCHUNK) load_chunk(((c + 1) & 1) * STAGE_BYTES, c + 1);

        uint32_t so = (uint32_t)((c & 1) * STAGE_BYTES);

#pragma unroll
        for (int mf = 0; mf < 4; ++mf)
            ldsm4(aa[0][mf], a_base + so + mf * 16 * LDSS);
#pragma unroll
        for (int bf = 0; bf < 2; ++bf)
            ldsm4(bb[0][bf], b_base + so + bf * 16 * LDSS);

#pragma unroll
        for (int kk = 0; kk < 4; ++kk) {
            int cur = kk & 1;
            if (kk < 3) {
                int nxt = cur ^ 1;
#pragma unroll
                for (int mf = 0; mf < 4; ++mf)
                    ldsm4(aa[nxt][mf], a_base + so + mf * 16 * LDSS + (kk + 1) * 32);
#pragma unroll
                for (int bf = 0; bf < 2; ++bf)
                    ldsm4(bb[nxt][bf], b_base + so + bf * 16 * LDSS + (kk + 1) * 32);
            }
#pragma unroll
            for (int mf = 0; mf < 4; ++mf)
#pragma unroll
                for (int nf = 0; nf < 4; ++nf)
                    mma16816(acc[mf][nf], aa[cur][mf],
                             bb[cur][nf >> 1][nf & 1], bb[cur][nf >> 1][(nf & 1) + 2]);
        }
    }

    // ---------------- epilogue: bias + scatter -------------------------------
    int g  = lane >> 2;
    int tc = (lane & 3) * 2;
    const float* bptr = bias + col0 + wn * 32 + tc;
    float2 bv[4];
#pragma unroll
    for (int nf = 0; nf < 4; ++nf)
        bv[nf] = make_float2(bptr[nf * 8], bptr[nf * 8 + 1]);

#pragma unroll
    for (int mf = 0; mf < 4; ++mf) {
#pragma unroll
        for (int rh = 0; rh < 2; ++rh) {
            int lr = wm * 64 + mf * 16 + rh * 8 + g;
            if (lr < rows) {
                float* orow = out + (size_t)sperm[lr] * OUT + col0 + wn * 32 + tc;
#pragma unroll
                for (int nf = 0; nf < 4; ++nf) {
                    float2 v = make_float2(acc[mf][nf][rh * 2]     + bv[nf].x,
                                           acc[mf][nf][rh * 2 + 1] + bv[nf].y);
                    *(float2*)(orow + nf * 8) = v;
                }
            }
        }
    }
}

// ---------------- launch -----------------------------------------------------
extern "C" void kernel_launch(void* const* d_in, const int* in_sizes, int n_in,
                              void* d_out, int out_size) {
    const float* x     = (const float*)d_in[0];
    const float* coeff = (const float*)d_in[1];
    const int*   bidx  = (const int*)d_in[2];
    const float* W     = (const float*)d_in[3];
    const float* bias  = (const float*)d_in[4];
    float*       out   = (float*)d_out;

    cudaFuncSetAttribute(gemm_kernel, cudaFuncAttributeMaxDynamicSharedMemorySize,
                         GSMEM);

    prep_kernel<<<512, 256>>>(bidx, x, W, coeff);
    gemm_kernel<<<dim3(OUT / TN, MAXT), 128, GSMEM>>>(bias, out);
}